// round 12
// baseline (speedup 1.0000x reference)
#include <cuda_runtime.h>
#include <cuda_bf16.h>
#include <cuda_fp16.h>
#include <math.h>
#include <stdint.h>

typedef unsigned long long u64;

#define B_TOTAL 8192
#define INDIM   784
#define NN      30
#define ND      20
#define NOUT    10
#define DK      16

// ---- k1 HMMA tiling ----
#define GNETS   6
#define NGRP    5
#define NT      15
#define KS49    49
#define NBAND   (B_TOTAL / 16)
#define HSTR    121

// ---- k2 tiling ----
#define RB    8
#define T2    640
#define UPAD  12
#define SLC   484                 // route-slice o-stride (mod 32 = 4)
#define SLCSZ (NOUT * SLC)        // 4840 floats per slice buffer

// ---- device scratch ----
__device__ float g_u[(size_t)B_TOTAL * NN * ND];
__device__ uint4 g_xhf[(size_t)NBAND * KS49 * 32];
__device__ uint4 g_xlf[(size_t)NBAND * KS49 * 32];
__device__ uint2 g_wbhf[(size_t)NGRP * KS49 * NT * 32];
__device__ uint2 g_wblf[(size_t)NGRP * KS49 * NT * 32];

// ---------------------------------------------------------------------------
// helpers
// ---------------------------------------------------------------------------
__device__ __forceinline__ uint32_t pbf2(float a, float b) {
    __nv_bfloat162 t = __floats2bfloat162_rn(a, b);
    return *(uint32_t*)&t;
}
__device__ __forceinline__ void split2(float v, float& h, float& l) {
    __nv_bfloat16 hb = __float2bfloat16(v);
    h = __bfloat162float(hb);
    l = v - h;
}
#define MMA_BF16(d, a, b) \
    asm volatile("mma.sync.aligned.m16n8k16.row.col.f32.bf16.bf16.f32 " \
        "{%0,%1,%2,%3}, {%4,%5,%6,%7}, {%8,%9}, {%0,%1,%2,%3};" \
        : "+f"((d)[0]), "+f"((d)[1]), "+f"((d)[2]), "+f"((d)[3]) \
        : "r"((a).x), "r"((a).y), "r"((a).z), "r"((a).w), \
          "r"((b).x), "r"((b).y))

__device__ __forceinline__ u64 pack2(float lo, float hi) {
    u64 r; asm("mov.b64 %0, {%1,%2};" : "=l"(r) : "f"(lo), "f"(hi)); return r;
}
__device__ __forceinline__ void unpack2(u64 v, float& lo, float& hi) {
    asm("mov.b64 {%0,%1}, %2;" : "=f"(lo), "=f"(hi) : "l"(v));
}
__device__ __forceinline__ void fma2(u64& d, u64 a, u64 b) {
    asm("fma.rn.f32x2 %0, %1, %2, %0;" : "+l"(d) : "l"(a), "l"(b));
}

// ---------------------------------------------------------------------------
// k0x: pack x into m16n8k16 A-fragment layout, split bf16 hi/lo
// ---------------------------------------------------------------------------
__global__ __launch_bounds__(256) void k0_pack_x(const float* __restrict__ x) {
    int gid = blockIdx.x * 256 + threadIdx.x;
    if (gid >= NBAND * KS49 * 32) return;
    int lane = gid & 31;
    int t    = gid >> 5;
    int ks   = t % KS49;
    int band = t / KS49;

    int r0 = band * 16 + (lane >> 2);
    int c0 = ks * 16 + (lane & 3) * 2;
    const float* p0 = x + (size_t)r0 * INDIM + c0;
    const float* p1 = p0 + 8 * INDIM;

    float v[8] = { p0[0], p0[1], p1[0], p1[1], p0[8], p0[9], p1[8], p1[9] };
    float h[8], l[8];
    #pragma unroll
    for (int i = 0; i < 8; i++) split2(v[i], h[i], l[i]);

    g_xhf[gid] = make_uint4(pbf2(h[0], h[1]), pbf2(h[2], h[3]),
                            pbf2(h[4], h[5]), pbf2(h[6], h[7]));
    g_xlf[gid] = make_uint4(pbf2(l[0], l[1]), pbf2(l[2], l[3]),
                            pbf2(l[4], l[5]), pbf2(l[6], l[7]));
}

// ---------------------------------------------------------------------------
// k0w: pack W1 into n8k16 B-fragment layout (col-major), hi/lo
// ---------------------------------------------------------------------------
__global__ __launch_bounds__(256) void k0_pack_w(const float* __restrict__ W1) {
    int gid = blockIdx.x * 256 + threadIdx.x;
    if (gid >= NGRP * KS49 * NT * 32) return;
    int lane = gid & 31;
    int t    = (gid >> 5) % NT;
    int ks   = ((gid >> 5) / NT) % KS49;
    int grp  = (gid >> 5) / (NT * KS49);

    int col = t * 8 + (lane >> 2);
    int net = grp * GNETS + col / ND;
    int c   = col % ND;
    int k0  = ks * 16 + (lane & 3) * 2;

    const float* wp = W1 + ((size_t)net * INDIM + k0) * ND + c;
    float v[4] = { wp[0], wp[ND], wp[8 * ND], wp[9 * ND] };
    float h[4], l[4];
    #pragma unroll
    for (int i = 0; i < 4; i++) split2(v[i], h[i], l[i]);

    g_wbhf[gid] = make_uint2(pbf2(h[0], h[1]), pbf2(h[2], h[3]));
    g_wblf[gid] = make_uint2(pbf2(l[0], l[1]), pbf2(l[2], l[3]));
}

// ---------------------------------------------------------------------------
// k1: HMMA split-bf16 GEMM1 + fused GEMM2/squash epilogue (frozen, verified)
// ---------------------------------------------------------------------------
__global__ __launch_bounds__(256, 2) void k1_mma(
    const float* __restrict__ b1,
    const float* __restrict__ W2,
    const float* __restrict__ b2)
{
    extern __shared__ __align__(16) float sm[];
    float* hs  = sm;
    float* ws2 = sm + 128 * HSTR;
    float* b1s = ws2 + GNETS * 400;
    float* b2s = b1s + GNETS * ND;

    const int tid  = threadIdx.x;
    const int w    = tid >> 5;
    const int lane = tid & 31;
    const int grp  = blockIdx.y;
    const int row0 = blockIdx.x * 128;

    for (int it = tid; it < GNETS * 400; it += 256)
        ws2[it] = W2[(size_t)(grp * GNETS) * 400 + it];
    if (tid < GNETS * ND) {
        b1s[tid] = b1[grp * GNETS * ND + tid];
        b2s[tid] = b2[grp * GNETS * ND + tid];
    }

    float acc[NT][4];
    #pragma unroll
    for (int t = 0; t < NT; t++)
        #pragma unroll
        for (int i = 0; i < 4; i++) acc[t][i] = 0.f;

    const int band = blockIdx.x * 8 + w;
    const uint4* pah = g_xhf + (size_t)band * KS49 * 32 + lane;
    const uint4* pal = g_xlf + (size_t)band * KS49 * 32 + lane;
    const uint2* pbh = g_wbhf + (size_t)grp * KS49 * NT * 32 + lane;
    const uint2* pbl = g_wblf + (size_t)grp * KS49 * NT * 32 + lane;

    uint4 ah = pah[0];
    uint4 al = pal[0];
    for (int ks = 0; ks < KS49; ks++) {
        uint4 ah_n, al_n;
        if (ks + 1 < KS49) {
            ah_n = pah[(ks + 1) * 32];
            al_n = pal[(ks + 1) * 32];
        }
        const uint2* bh = pbh + ks * NT * 32;
        const uint2* bl = pbl + ks * NT * 32;
        #pragma unroll
        for (int t = 0; t < NT; t++) {
            uint2 vh = bh[t * 32];
            uint2 vl = bl[t * 32];
            MMA_BF16(acc[t], ah, vh);
            MMA_BF16(acc[t], al, vh);
            MMA_BF16(acc[t], ah, vl);
        }
        ah = ah_n; al = al_n;
    }

    {
        const int rlo = w * 16 + (lane >> 2);
        const int cb  = (lane & 3) * 2;
        #pragma unroll
        for (int t = 0; t < NT; t++) {
            int col = t * 8 + cb;
            hs[rlo * HSTR + col]           = acc[t][0];
            hs[rlo * HSTR + col + 1]       = acc[t][1];
            hs[(rlo + 8) * HSTR + col]     = acc[t][2];
            hs[(rlo + 8) * HSTR + col + 1] = acc[t][3];
        }
    }
    __syncthreads();

    for (int task = tid; task < 128 * GNETS; task += 256) {
        const int row = task / GNETS;
        const int g   = task % GNETS;
        const int net = grp * GNETS + g;
        float h[ND];
        #pragma unroll
        for (int c = 0; c < ND; c++) {
            float v = hs[row * HSTR + g * ND + c] + b1s[g * ND + c];
            h[c] = v > 0.f ? v : 0.f;
        }
        float h2[ND];
        float sq = 0.f;
        #pragma unroll
        for (int e = 0; e < ND; e++) {
            float s = b2s[g * ND + e];
            #pragma unroll
            for (int d = 0; d < ND; d++) s += h[d] * ws2[g * 400 + d * ND + e];
            s = s > 0.f ? s : 0.f;
            h2[e] = s;
            sq += s * s;
        }
        float scale = (sq / (1.f + sq)) / sqrtf(sq);
        float* up = g_u + (size_t)(row0 + row) * (NN * ND) + net * ND;
        #pragma unroll
        for (int e4 = 0; e4 < 5; e4++)
            *(float4*)(up + e4 * 4) = make_float4(scale * h2[e4*4],   scale * h2[e4*4+1],
                                                  scale * h2[e4*4+2], scale * h2[e4*4+3]);
    }
}

// ---------------------------------------------------------------------------
// k2: fused priors + routing, with route d-slice staged through smem
// (double-buffered, coalesced). Priors fp16 in smem. grid = B/8, block 640.
// ---------------------------------------------------------------------------
__global__ __launch_bounds__(T2, 1) void k2_route(
    const float* __restrict__ route,  // [10, 30, 20, 16]
    float* __restrict__ out)          // [B, 10, 16]
{
    extern __shared__ __align__(16) char smraw[];
    float*  u_s = (float*)smraw;                        // [600][UPAD] 28800 B
    __half* p_h = (__half*)(smraw + 28800);             // [8][10][30][16] 76800 B
    float*  slc = (float*)(smraw + 28800 + 76800);      // 2 x [10][SLC] 38720 B
    // routing overlay of u_s region (valid after priors):
    float*  l_s  = (float*)smraw;                       // [8][300]
    float*  pr_s = l_s + RB * NOUT * NN;                // [8][300]
    float*  v_s  = pr_s + RB * NOUT * NN;               // [8][160]

    const int tid = threadIdx.x;
    const int r0  = blockIdx.x * RB;

    // slice loader indices (1200 float4 per slice; thread covers idx, idx+640)
    const int li0 = tid;
    const int li1 = tid + T2;

    // load u for 8 rows, transposed [c][row]
    for (int it = tid; it < RB * NN * ND; it += T2) {
        int r = it / (NN * ND);
        int c = it % (NN * ND);
        u_s[c * UPAD + r] = g_u[(size_t)(r0 + r) * (NN * ND) + c];
    }

    // preload route slice d=0 (coalesced)
    {
        #pragma unroll
        for (int t = 0; t < 2; t++) {
            int idx = t == 0 ? li0 : li1;
            if (idx < 1200) {
                int c = idx >> 2, q = idx & 3;
                int o = c / NN, n = c % NN;
                float4 v = *(const float4*)(route + (size_t)((o * NN + n) * ND + 0) * DK + q * 4);
                *(float4*)(slc + o * SLC + n * DK + q * 4) = v;
            }
        }
    }
    __syncthreads();

    // ---- priors: thread = (n, o, kg); route from staged smem slice ----
    const int n_  = tid / 20;
    const int oo_ = tid % 20;
    const int o_  = oo_ >> 1;
    const int kg_ = oo_ & 1;
    const float* up_  = u_s + (n_ * ND) * UPAD;
    const int slcoff  = o_ * SLC + n_ * DK + kg_ * 8;

    u64 acc[4][8];
    #pragma unroll
    for (int i = 0; i < 4; i++)
        #pragma unroll
        for (int j = 0; j < 8; j++) acc[i][j] = 0ull;

    for (int d = 0; d < ND; d++) {
        const float* cur = slc + (d & 1) * SLCSZ;
        float* nxt = slc + ((d + 1) & 1) * SLCSZ;

        // issue next-slice global loads first (latency hidden by compute)
        float4 nx0, nx1;
        const bool more = (d + 1 < ND);
        if (more) {
            int c0 = li0 >> 2, q0 = li0 & 3;
            int oA = c0 / NN, nA = c0 % NN;
            nx0 = *(const float4*)(route + (size_t)((oA * NN + nA) * ND + d + 1) * DK + q0 * 4);
            if (li1 < 1200) {
                int c1 = li1 >> 2, q1 = li1 & 3;
                int oB = c1 / NN, nB = c1 % NN;
                nx1 = *(const float4*)(route + (size_t)((oB * NN + nB) * ND + d + 1) * DK + q1 * 4);
            }
        }

        // compute this d
        if (tid < 600) {
            ulonglong2 ua = *(const ulonglong2*)(up_ + d * UPAD);
            ulonglong2 ub = *(const ulonglong2*)(up_ + d * UPAD + 4);
            u64 uv[4] = {ua.x, ua.y, ub.x, ub.y};
            float4 ra = *(const float4*)(cur + slcoff);
            float4 rb = *(const float4*)(cur + slcoff + 4);
            u64 wv[8] = {pack2(ra.x, ra.x), pack2(ra.y, ra.y),
                         pack2(ra.z, ra.z), pack2(ra.w, ra.w),
                         pack2(rb.x, rb.x), pack2(rb.y, rb.y),
                         pack2(rb.z, rb.z), pack2(rb.w, rb.w)};
            #pragma unroll
            for (int i = 0; i < 4; i++)
                #pragma unroll
                for (int j = 0; j < 8; j++)
                    fma2(acc[i][j], uv[i], wv[j]);
        }

        // store next slice
        if (more) {
            {
                int c0 = li0 >> 2, q0 = li0 & 3;
                int oA = c0 / NN, nA = c0 % NN;
                *(float4*)(nxt + oA * SLC + nA * DK + q0 * 4) = nx0;
            }
            if (li1 < 1200) {
                int c1 = li1 >> 2, q1 = li1 & 3;
                int oB = c1 / NN, nB = c1 % NN;
                *(float4*)(nxt + oB * SLC + nB * DK + q1 * 4) = nx1;
            }
        }
        __syncthreads();
    }

    // acc -> fp16 priors in smem [r][o][n][16]
    if (tid < 600) {
        #pragma unroll
        for (int i = 0; i < 4; i++) {
            float lo[8], hi[8];
            #pragma unroll
            for (int j = 0; j < 8; j++) unpack2(acc[i][j], lo[j], hi[j]);
            uint4 qlo, qhi;
            __half2* a = (__half2*)&qlo;
            __half2* b = (__half2*)&qhi;
            #pragma unroll
            for (int p = 0; p < 4; p++) {
                a[p] = __floats2half2_rn(lo[2*p], lo[2*p + 1]);
                b[p] = __floats2half2_rn(hi[2*p], hi[2*p + 1]);
            }
            *(uint4*)&p_h[((((2*i    ) * NOUT + o_) * NN + n_) * DK) + kg_ * 8] = qlo;
            *(uint4*)&p_h[((((2*i + 1) * NOUT + o_) * NN + n_) * DK) + kg_ * 8] = qhi;
        }
    }
    __syncthreads();   // retires u_s reads before overlay writes

    // ---- dynamic routing, 3 iterations (fp16 priors, vectorized) ----
    for (int iter = 0; iter < 3; iter++) {
        if (iter > 0) {
            if (tid < RB * NN) {
                int r = tid / NN, n = tid % NN;
                float l[NOUT];
                float mx = -1e30f;
                #pragma unroll
                for (int o = 0; o < NOUT; o++) {
                    l[o] = l_s[(r * NOUT + o) * NN + n];
                    mx = fmaxf(mx, l[o]);
                }
                float ssum = 0.f;
                #pragma unroll
                for (int o = 0; o < NOUT; o++) { l[o] = expf(l[o] - mx); ssum += l[o]; }
                float inv = 1.f / ssum;
                #pragma unroll
                for (int o = 0; o < NOUT; o++)
                    pr_s[(r * NOUT + o) * NN + n] = l[o] * inv;
            }
            __syncthreads();
        }

        // s-pass: item = (ro, khalf)
        if (tid < RB * NOUT * 2) {
            int kh = tid & 1;
            int ro = tid >> 1;
            const __half* pp = p_h + ro * (NN * DK) + kh * 8;
            float s8[8] = {0,0,0,0,0,0,0,0};
            #pragma unroll 5
            for (int n = 0; n < NN; n++) {
                uint4 q = *(const uint4*)(pp + n * DK);
                __half2* hx = (__half2*)&q;
                float w = (iter == 0) ? 1.f : pr_s[ro * NN + n];
                #pragma unroll
                for (int p = 0; p < 4; p++) {
                    float2 f = __half22float2(hx[p]);
                    s8[2*p]   += w * f.x;
                    s8[2*p+1] += w * f.y;
                }
            }
            float mul = (iter == 0) ? 0.1f : 1.f;
            #pragma unroll
            for (int j = 0; j < 8; j++) v_s[ro * DK + kh * 8 + j] = s8[j] * mul;
        }
        __syncthreads();

        // squash per (r,o)
        if (tid < RB * NOUT) {
            float* vp = v_s + tid * DK;
            float sq = 0.f;
            #pragma unroll
            for (int k = 0; k < DK; k++) sq += vp[k] * vp[k];
            float scale = (sq / (1.f + sq)) / sqrtf(sq);
            #pragma unroll
            for (int k = 0; k < DK; k++) vp[k] *= scale;
        }
        __syncthreads();

        if (iter < 2) {
            for (int it = tid; it < RB * NOUT * NN; it += T2) {
                int n  = it % NN;
                int ro = it / NN;
                const __half* pp = p_h + ro * (NN * DK) + n * DK;
                const float* vp = v_s + ro * DK;
                uint4 q0 = *(const uint4*)pp;
                uint4 q1 = *(const uint4*)(pp + 8);
                __half2* h0 = (__half2*)&q0;
                __half2* h1 = (__half2*)&q1;
                float s = 0.f;
                #pragma unroll
                for (int p = 0; p < 4; p++) {
                    float2 f0 = __half22float2(h0[p]);
                    float2 f1 = __half22float2(h1[p]);
                    s += f0.x * vp[2*p]     + f0.y * vp[2*p + 1];
                    s += f1.x * vp[8 + 2*p] + f1.y * vp[8 + 2*p + 1];
                }
                l_s[ro * NN + n] = (iter == 0) ? s : (l_s[ro * NN + n] + s);
            }
            __syncthreads();
        }
    }

    // write output [B,10,16]
    for (int it = tid; it < RB * NOUT * DK; it += T2) {
        int r = it / (NOUT * DK);
        out[(size_t)(r0 + r) * (NOUT * DK) + (it % (NOUT * DK))] = v_s[it];
    }
}

// ---------------------------------------------------------------------------
extern "C" void kernel_launch(void* const* d_in, const int* in_sizes, int n_in,
                              void* d_out, int out_size)
{
    const float* x     = (const float*)d_in[0];
    const float* W1    = (const float*)d_in[1];
    const float* b1    = (const float*)d_in[2];
    const float* W2    = (const float*)d_in[3];
    const float* b2    = (const float*)d_in[4];
    const float* route = (const float*)d_in[5];
    float* out = (float*)d_out;

    // pack inputs into HMMA fragment layout (bf16 hi/lo)
    k0_pack_x<<<(NBAND * KS49 * 32 + 255) / 256, 256>>>(x);
    k0_pack_w<<<(NGRP * KS49 * NT * 32 + 255) / 256, 256>>>(W1);

    // tensor-core GEMM1 + fused epilogue
    const int smem1 = (128 * HSTR + GNETS * 400 + 2 * GNETS * ND) * (int)sizeof(float);
    cudaFuncSetAttribute(k1_mma, cudaFuncAttributeMaxDynamicSharedMemorySize, smem1);
    dim3 g1(B_TOTAL / 128, NGRP);
    k1_mma<<<g1, 256, smem1>>>(b1, W2, b2);

    // fused priors + routing (staged route slices + fp16 priors in smem)
    const int smem2 = 28800 + 76800 + 2 * SLCSZ * (int)sizeof(float);  // 144320 B
    cudaFuncSetAttribute(k2_route, cudaFuncAttributeMaxDynamicSharedMemorySize, smem2);
    k2_route<<<B_TOTAL / RB, T2, smem2>>>(route, out);
}

// round 13
// speedup vs baseline: 1.7251x; 1.7251x over previous
#include <cuda_runtime.h>
#include <cuda_bf16.h>
#include <cuda_fp16.h>
#include <math.h>
#include <stdint.h>

typedef unsigned long long u64;

#define B_TOTAL 8192
#define INDIM   784
#define NN      30
#define ND      20
#define NOUT    10
#define DK      16

// ---- k1 HMMA tiling ----
#define GNETS   6
#define NGRP    5
#define NT      15
#define KS49    49
#define NBAND   (B_TOTAL / 16)
#define HSTR    121

// ---- k2 tiling ----
#define RB    8
#define T2    640
#define UPAD  12

// ---- device scratch ----
__device__ float  g_u[(size_t)B_TOTAL * NN * ND];
__device__ __half g_rh[(size_t)NOUT * NN * 2 * 160];     // route fp16 [o][n][kg][d][8k]
__device__ uint4  g_xhf[(size_t)NBAND * KS49 * 32];
__device__ uint4  g_xlf[(size_t)NBAND * KS49 * 32];
__device__ uint2  g_wbhf[(size_t)NGRP * KS49 * NT * 32];
__device__ uint2  g_wblf[(size_t)NGRP * KS49 * NT * 32];

// ---------------------------------------------------------------------------
// helpers
// ---------------------------------------------------------------------------
__device__ __forceinline__ uint32_t pbf2(float a, float b) {
    __nv_bfloat162 t = __floats2bfloat162_rn(a, b);
    return *(uint32_t*)&t;
}
__device__ __forceinline__ void split2(float v, float& h, float& l) {
    __nv_bfloat16 hb = __float2bfloat16(v);
    h = __bfloat162float(hb);
    l = v - h;
}
#define MMA_BF16(d, a, b) \
    asm volatile("mma.sync.aligned.m16n8k16.row.col.f32.bf16.bf16.f32 " \
        "{%0,%1,%2,%3}, {%4,%5,%6,%7}, {%8,%9}, {%0,%1,%2,%3};" \
        : "+f"((d)[0]), "+f"((d)[1]), "+f"((d)[2]), "+f"((d)[3]) \
        : "r"((a).x), "r"((a).y), "r"((a).z), "r"((a).w), \
          "r"((b).x), "r"((b).y))

__device__ __forceinline__ u64 pack2(float lo, float hi) {
    u64 r; asm("mov.b64 %0, {%1,%2};" : "=l"(r) : "f"(lo), "f"(hi)); return r;
}
__device__ __forceinline__ void unpack2(u64 v, float& lo, float& hi) {
    asm("mov.b64 {%0,%1}, %2;" : "=f"(lo), "=f"(hi) : "l"(v));
}
__device__ __forceinline__ void fma2(u64& d, u64 a, u64 b) {
    asm("fma.rn.f32x2 %0, %1, %2, %0;" : "+l"(d) : "l"(a), "l"(b));
}

// ---------------------------------------------------------------------------
// k0x: pack x into m16n8k16 A-fragment layout, split bf16 hi/lo
// ---------------------------------------------------------------------------
__global__ __launch_bounds__(256) void k0_pack_x(const float* __restrict__ x) {
    int gid = blockIdx.x * 256 + threadIdx.x;
    if (gid >= NBAND * KS49 * 32) return;
    int lane = gid & 31;
    int t    = gid >> 5;
    int ks   = t % KS49;
    int band = t / KS49;

    int r0 = band * 16 + (lane >> 2);
    int c0 = ks * 16 + (lane & 3) * 2;
    const float* p0 = x + (size_t)r0 * INDIM + c0;
    const float* p1 = p0 + 8 * INDIM;

    float v[8] = { p0[0], p0[1], p1[0], p1[1], p0[8], p0[9], p1[8], p1[9] };
    float h[8], l[8];
    #pragma unroll
    for (int i = 0; i < 8; i++) split2(v[i], h[i], l[i]);

    g_xhf[gid] = make_uint4(pbf2(h[0], h[1]), pbf2(h[2], h[3]),
                            pbf2(h[4], h[5]), pbf2(h[6], h[7]));
    g_xlf[gid] = make_uint4(pbf2(l[0], l[1]), pbf2(l[2], l[3]),
                            pbf2(l[4], l[5]), pbf2(l[6], l[7]));
}

// ---------------------------------------------------------------------------
// k0w: pack W1 into n8k16 B-fragment layout (col-major), hi/lo
// ---------------------------------------------------------------------------
__global__ __launch_bounds__(256) void k0_pack_w(const float* __restrict__ W1) {
    int gid = blockIdx.x * 256 + threadIdx.x;
    if (gid >= NGRP * KS49 * NT * 32) return;
    int lane = gid & 31;
    int t    = (gid >> 5) % NT;
    int ks   = ((gid >> 5) / NT) % KS49;
    int grp  = (gid >> 5) / (NT * KS49);

    int col = t * 8 + (lane >> 2);
    int net = grp * GNETS + col / ND;
    int c   = col % ND;
    int k0  = ks * 16 + (lane & 3) * 2;

    const float* wp = W1 + ((size_t)net * INDIM + k0) * ND + c;
    float v[4] = { wp[0], wp[ND], wp[8 * ND], wp[9 * ND] };
    float h[4], l[4];
    #pragma unroll
    for (int i = 0; i < 4; i++) split2(v[i], h[i], l[i]);

    g_wbhf[gid] = make_uint2(pbf2(h[0], h[1]), pbf2(h[2], h[3]));
    g_wblf[gid] = make_uint2(pbf2(l[0], l[1]), pbf2(l[2], l[3]));
}

// ---------------------------------------------------------------------------
// k0r: route -> fp16, reordered [o][n][kg][d][8k] (per-thread-contiguous)
// ---------------------------------------------------------------------------
__global__ __launch_bounds__(256) void k0_pack_r(const float* __restrict__ route) {
    int gid = blockIdx.x * 256 + threadIdx.x;      // ((o*30+n)*2+kg)*20 + d
    if (gid >= NOUT * NN * 2 * ND) return;
    int d  = gid % ND;
    int kg = (gid / ND) & 1;
    int on = gid / (ND * 2);                       // o*30+n
    const float* src = route + ((size_t)on * ND + d) * DK + kg * 8;
    float4 a = *(const float4*)src;
    float4 b = *(const float4*)(src + 4);
    uint4 q;
    __half2* hh = (__half2*)&q;
    hh[0] = __floats2half2_rn(a.x, a.y);
    hh[1] = __floats2half2_rn(a.z, a.w);
    hh[2] = __floats2half2_rn(b.x, b.y);
    hh[3] = __floats2half2_rn(b.z, b.w);
    *(uint4*)(g_rh + (size_t)gid * 8) = q;
}

// ---------------------------------------------------------------------------
// k1: HMMA split-bf16 GEMM1 + fused GEMM2/squash epilogue (frozen, verified)
// ---------------------------------------------------------------------------
__global__ __launch_bounds__(256, 2) void k1_mma(
    const float* __restrict__ b1,
    const float* __restrict__ W2,
    const float* __restrict__ b2)
{
    extern __shared__ __align__(16) float sm[];
    float* hs  = sm;
    float* ws2 = sm + 128 * HSTR;
    float* b1s = ws2 + GNETS * 400;
    float* b2s = b1s + GNETS * ND;

    const int tid  = threadIdx.x;
    const int w    = tid >> 5;
    const int lane = tid & 31;
    const int grp  = blockIdx.y;
    const int row0 = blockIdx.x * 128;

    for (int it = tid; it < GNETS * 400; it += 256)
        ws2[it] = W2[(size_t)(grp * GNETS) * 400 + it];
    if (tid < GNETS * ND) {
        b1s[tid] = b1[grp * GNETS * ND + tid];
        b2s[tid] = b2[grp * GNETS * ND + tid];
    }

    float acc[NT][4];
    #pragma unroll
    for (int t = 0; t < NT; t++)
        #pragma unroll
        for (int i = 0; i < 4; i++) acc[t][i] = 0.f;

    const int band = blockIdx.x * 8 + w;
    const uint4* pah = g_xhf + (size_t)band * KS49 * 32 + lane;
    const uint4* pal = g_xlf + (size_t)band * KS49 * 32 + lane;
    const uint2* pbh = g_wbhf + (size_t)grp * KS49 * NT * 32 + lane;
    const uint2* pbl = g_wblf + (size_t)grp * KS49 * NT * 32 + lane;

    uint4 ah = pah[0];
    uint4 al = pal[0];
    for (int ks = 0; ks < KS49; ks++) {
        uint4 ah_n, al_n;
        if (ks + 1 < KS49) {
            ah_n = pah[(ks + 1) * 32];
            al_n = pal[(ks + 1) * 32];
        }
        const uint2* bh = pbh + ks * NT * 32;
        const uint2* bl = pbl + ks * NT * 32;
        #pragma unroll
        for (int t = 0; t < NT; t++) {
            uint2 vh = bh[t * 32];
            uint2 vl = bl[t * 32];
            MMA_BF16(acc[t], ah, vh);
            MMA_BF16(acc[t], al, vh);
            MMA_BF16(acc[t], ah, vl);
        }
        ah = ah_n; al = al_n;
    }

    {
        const int rlo = w * 16 + (lane >> 2);
        const int cb  = (lane & 3) * 2;
        #pragma unroll
        for (int t = 0; t < NT; t++) {
            int col = t * 8 + cb;
            hs[rlo * HSTR + col]           = acc[t][0];
            hs[rlo * HSTR + col + 1]       = acc[t][1];
            hs[(rlo + 8) * HSTR + col]     = acc[t][2];
            hs[(rlo + 8) * HSTR + col + 1] = acc[t][3];
        }
    }
    __syncthreads();

    for (int task = tid; task < 128 * GNETS; task += 256) {
        const int row = task / GNETS;
        const int g   = task % GNETS;
        const int net = grp * GNETS + g;
        float h[ND];
        #pragma unroll
        for (int c = 0; c < ND; c++) {
            float v = hs[row * HSTR + g * ND + c] + b1s[g * ND + c];
            h[c] = v > 0.f ? v : 0.f;
        }
        float h2[ND];
        float sq = 0.f;
        #pragma unroll
        for (int e = 0; e < ND; e++) {
            float s = b2s[g * ND + e];
            #pragma unroll
            for (int d = 0; d < ND; d++) s += h[d] * ws2[g * 400 + d * ND + e];
            s = s > 0.f ? s : 0.f;
            h2[e] = s;
            sq += s * s;
        }
        float scale = (sq / (1.f + sq)) / sqrtf(sq);
        float* up = g_u + (size_t)(row0 + row) * (NN * ND) + net * ND;
        #pragma unroll
        for (int e4 = 0; e4 < 5; e4++)
            *(float4*)(up + e4 * 4) = make_float4(scale * h2[e4*4],   scale * h2[e4*4+1],
                                                  scale * h2[e4*4+2], scale * h2[e4*4+3]);
    }
}

// ---------------------------------------------------------------------------
// k2: fused priors + routing. Priors read route from fp16 reordered g_rh
// (20 contiguous LDG.128/thread, full MLP). Priors fp16 in smem.
// grid = B/8, block 640, 105.6KB smem.
// ---------------------------------------------------------------------------
__global__ __launch_bounds__(T2, 1) void k2_route(float* __restrict__ out) {
    extern __shared__ __align__(16) char smraw[];
    float*  u_s = (float*)smraw;                       // [600][UPAD] (priors phase)
    // overlay (valid after priors barrier):
    float*  l_s  = (float*)smraw;                      // [8][300]
    float*  pr_s = l_s + RB * NOUT * NN;               // [8][300]
    float*  v_s  = pr_s + RB * NOUT * NN;              // [8][160]
    __half* p_h  = (__half*)(smraw + 600 * UPAD * 4);  // [8][10][30][16] fp16

    const int tid = threadIdx.x;
    const int r0  = blockIdx.x * RB;

    // load u for 8 rows, transposed [c][row]
    for (int it = tid; it < RB * NN * ND; it += T2) {
        int r = it / (NN * ND);
        int c = it % (NN * ND);
        u_s[c * UPAD + r] = g_u[(size_t)(r0 + r) * (NN * ND) + c];
    }
    __syncthreads();

    // ---- priors: thread = (n, o, kg); route from fp16 contiguous stream ----
    if (tid < 600) {
        const int n  = tid / 20;
        const int oo = tid % 20;
        const int o  = oo >> 1;
        const int kg = oo & 1;

        u64 acc[4][8];
        #pragma unroll
        for (int i = 0; i < 4; i++)
            #pragma unroll
            for (int j = 0; j < 8; j++) acc[i][j] = 0ull;

        const __half* rp = g_rh + ((size_t)(o * NN + n) * 2 + kg) * 160;
        const float*  up = u_s + (n * ND) * UPAD;

        #pragma unroll 4
        for (int d = 0; d < ND; d++) {
            ulonglong2 ua = *(const ulonglong2*)(up + d * UPAD);
            ulonglong2 ub = *(const ulonglong2*)(up + d * UPAD + 4);
            u64 uv[4] = {ua.x, ua.y, ub.x, ub.y};
            uint4 q = *(const uint4*)(rp + d * 8);     // 8 k-values fp16
            __half2* hh = (__half2*)&q;
            float2 f0 = __half22float2(hh[0]);
            float2 f1 = __half22float2(hh[1]);
            float2 f2 = __half22float2(hh[2]);
            float2 f3 = __half22float2(hh[3]);
            u64 wv[8] = {pack2(f0.x, f0.x), pack2(f0.y, f0.y),
                         pack2(f1.x, f1.x), pack2(f1.y, f1.y),
                         pack2(f2.x, f2.x), pack2(f2.y, f2.y),
                         pack2(f3.x, f3.x), pack2(f3.y, f3.y)};
            #pragma unroll
            for (int i = 0; i < 4; i++)
                #pragma unroll
                for (int j = 0; j < 8; j++)
                    fma2(acc[i][j], uv[i], wv[j]);
        }

        // acc -> fp16 priors in smem [r][o][n][16]
        #pragma unroll
        for (int i = 0; i < 4; i++) {
            float lo[8], hi[8];
            #pragma unroll
            for (int j = 0; j < 8; j++) unpack2(acc[i][j], lo[j], hi[j]);
            uint4 qlo, qhi;
            __half2* a = (__half2*)&qlo;
            __half2* b = (__half2*)&qhi;
            #pragma unroll
            for (int p = 0; p < 4; p++) {
                a[p] = __floats2half2_rn(lo[2*p], lo[2*p + 1]);
                b[p] = __floats2half2_rn(hi[2*p], hi[2*p + 1]);
            }
            *(uint4*)&p_h[((((2*i    ) * NOUT + o) * NN + n) * DK) + kg * 8] = qlo;
            *(uint4*)&p_h[((((2*i + 1) * NOUT + o) * NN + n) * DK) + kg * 8] = qhi;
        }
    }
    __syncthreads();   // retires u_s reads before overlay writes

    // ---- dynamic routing, 3 iterations (fp16 priors, vectorized) ----
    for (int iter = 0; iter < 3; iter++) {
        if (iter > 0) {
            if (tid < RB * NN) {
                int r = tid / NN, n = tid % NN;
                float l[NOUT];
                float mx = -1e30f;
                #pragma unroll
                for (int o = 0; o < NOUT; o++) {
                    l[o] = l_s[(r * NOUT + o) * NN + n];
                    mx = fmaxf(mx, l[o]);
                }
                float ssum = 0.f;
                #pragma unroll
                for (int o = 0; o < NOUT; o++) { l[o] = expf(l[o] - mx); ssum += l[o]; }
                float inv = 1.f / ssum;
                #pragma unroll
                for (int o = 0; o < NOUT; o++)
                    pr_s[(r * NOUT + o) * NN + n] = l[o] * inv;
            }
            __syncthreads();
        }

        // s-pass: item = (ro, khalf)
        if (tid < RB * NOUT * 2) {
            int kh = tid & 1;
            int ro = tid >> 1;
            const __half* pp = p_h + ro * (NN * DK) + kh * 8;
            float s8[8] = {0,0,0,0,0,0,0,0};
            #pragma unroll 5
            for (int n = 0; n < NN; n++) {
                uint4 q = *(const uint4*)(pp + n * DK);
                __half2* hx = (__half2*)&q;
                float w = (iter == 0) ? 1.f : pr_s[ro * NN + n];
                #pragma unroll
                for (int p = 0; p < 4; p++) {
                    float2 f = __half22float2(hx[p]);
                    s8[2*p]   += w * f.x;
                    s8[2*p+1] += w * f.y;
                }
            }
            float mul = (iter == 0) ? 0.1f : 1.f;
            #pragma unroll
            for (int j = 0; j < 8; j++) v_s[ro * DK + kh * 8 + j] = s8[j] * mul;
        }
        __syncthreads();

        // squash per (r,o)
        if (tid < RB * NOUT) {
            float* vp = v_s + tid * DK;
            float sq = 0.f;
            #pragma unroll
            for (int k = 0; k < DK; k++) sq += vp[k] * vp[k];
            float scale = (sq / (1.f + sq)) / sqrtf(sq);
            #pragma unroll
            for (int k = 0; k < DK; k++) vp[k] *= scale;
        }
        __syncthreads();

        if (iter < 2) {
            for (int it = tid; it < RB * NOUT * NN; it += T2) {
                int n  = it % NN;
                int ro = it / NN;
                const __half* pp = p_h + ro * (NN * DK) + n * DK;
                const float* vp = v_s + ro * DK;
                uint4 q0 = *(const uint4*)pp;
                uint4 q1 = *(const uint4*)(pp + 8);
                __half2* h0 = (__half2*)&q0;
                __half2* h1 = (__half2*)&q1;
                float s = 0.f;
                #pragma unroll
                for (int p = 0; p < 4; p++) {
                    float2 f0 = __half22float2(h0[p]);
                    float2 f1 = __half22float2(h1[p]);
                    s += f0.x * vp[2*p]     + f0.y * vp[2*p + 1];
                    s += f1.x * vp[8 + 2*p] + f1.y * vp[8 + 2*p + 1];
                }
                l_s[ro * NN + n] = (iter == 0) ? s : (l_s[ro * NN + n] + s);
            }
            __syncthreads();
        }
    }

    // write output [B,10,16]
    for (int it = tid; it < RB * NOUT * DK; it += T2) {
        int r = it / (NOUT * DK);
        out[(size_t)(r0 + r) * (NOUT * DK) + (it % (NOUT * DK))] = v_s[it];
    }
}

// ---------------------------------------------------------------------------
extern "C" void kernel_launch(void* const* d_in, const int* in_sizes, int n_in,
                              void* d_out, int out_size)
{
    const float* x     = (const float*)d_in[0];
    const float* W1    = (const float*)d_in[1];
    const float* b1    = (const float*)d_in[2];
    const float* W2    = (const float*)d_in[3];
    const float* b2    = (const float*)d_in[4];
    const float* route = (const float*)d_in[5];
    float* out = (float*)d_out;

    // pack inputs (HMMA frags bf16 hi/lo; route fp16 reordered)
    k0_pack_x<<<(NBAND * KS49 * 32 + 255) / 256, 256>>>(x);
    k0_pack_w<<<(NGRP * KS49 * NT * 32 + 255) / 256, 256>>>(W1);
    k0_pack_r<<<(NOUT * NN * 2 * ND + 255) / 256, 256>>>(route);

    // tensor-core GEMM1 + fused epilogue
    const int smem1 = (128 * HSTR + GNETS * 400 + 2 * GNETS * ND) * (int)sizeof(float);
    cudaFuncSetAttribute(k1_mma, cudaFuncAttributeMaxDynamicSharedMemorySize, smem1);
    dim3 g1(B_TOTAL / 128, NGRP);
    k1_mma<<<g1, 256, smem1>>>(b1, W2, b2);

    // fused priors + routing (fp16 route stream + fp16 priors in smem)
    const int smem2 = 600 * UPAD * (int)sizeof(float)
                    + RB * NOUT * NN * DK * (int)sizeof(__half);   // 105,600 B
    cudaFuncSetAttribute(k2_route, cudaFuncAttributeMaxDynamicSharedMemorySize, smem2);
    k2_route<<<B_TOTAL / RB, T2, smem2>>>(out);
}

// round 15
// speedup vs baseline: 1.7430x; 1.0103x over previous
#include <cuda_runtime.h>
#include <cuda_bf16.h>
#include <cuda_fp16.h>
#include <math.h>
#include <stdint.h>

typedef unsigned long long u64;

#define B_TOTAL 8192
#define INDIM   784
#define NN      30
#define ND      20
#define NOUT    10
#define DK      16

// ---- k1 HMMA tiling ----
#define GNETS   6
#define NGRP    5
#define NT      15
#define KS49    49
#define NBAND   (B_TOTAL / 16)
#define HSTR    121
#define BSTG    480               // uint4 per B stage (240 hi + 240 lo)

// ---- k2 tiling ----
#define RB    8
#define T2    640
#define UPAD  12

// ---- device scratch ----
__device__ float  g_u[(size_t)B_TOTAL * NN * ND];
__device__ __half g_rh[(size_t)NOUT * NN * 2 * 160];     // route fp16 [o][n][kg][d][8k]
__device__ uint4  g_xhf[(size_t)NBAND * KS49 * 32];
__device__ uint4  g_xlf[(size_t)NBAND * KS49 * 32];
__device__ uint2  g_wbhf[(size_t)NGRP * KS49 * NT * 32];
__device__ uint2  g_wblf[(size_t)NGRP * KS49 * NT * 32];

// ---------------------------------------------------------------------------
// helpers
// ---------------------------------------------------------------------------
__device__ __forceinline__ uint32_t pbf2(float a, float b) {
    __nv_bfloat162 t = __floats2bfloat162_rn(a, b);
    return *(uint32_t*)&t;
}
__device__ __forceinline__ void split2(float v, float& h, float& l) {
    __nv_bfloat16 hb = __float2bfloat16(v);
    h = __bfloat162float(hb);
    l = v - h;
}
#define MMA_BF16(d, a, b) \
    asm volatile("mma.sync.aligned.m16n8k16.row.col.f32.bf16.bf16.f32 " \
        "{%0,%1,%2,%3}, {%4,%5,%6,%7}, {%8,%9}, {%0,%1,%2,%3};" \
        : "+f"((d)[0]), "+f"((d)[1]), "+f"((d)[2]), "+f"((d)[3]) \
        : "r"((a).x), "r"((a).y), "r"((a).z), "r"((a).w), \
          "r"((b).x), "r"((b).y))

__device__ __forceinline__ u64 pack2(float lo, float hi) {
    u64 r; asm("mov.b64 %0, {%1,%2};" : "=l"(r) : "f"(lo), "f"(hi)); return r;
}
__device__ __forceinline__ void unpack2(u64 v, float& lo, float& hi) {
    asm("mov.b64 {%0,%1}, %2;" : "=f"(lo), "=f"(hi) : "l"(v));
}
__device__ __forceinline__ void fma2(u64& d, u64 a, u64 b) {
    asm("fma.rn.f32x2 %0, %1, %2, %0;" : "+l"(d) : "l"(a), "l"(b));
}

// ---------------------------------------------------------------------------
// k0x: pack x into m16n8k16 A-fragment layout, split bf16 hi/lo
// ---------------------------------------------------------------------------
__global__ __launch_bounds__(256) void k0_pack_x(const float* __restrict__ x) {
    int gid = blockIdx.x * 256 + threadIdx.x;
    if (gid >= NBAND * KS49 * 32) return;
    int lane = gid & 31;
    int t    = gid >> 5;
    int ks   = t % KS49;
    int band = t / KS49;

    int r0 = band * 16 + (lane >> 2);
    int c0 = ks * 16 + (lane & 3) * 2;
    const float* p0 = x + (size_t)r0 * INDIM + c0;
    const float* p1 = p0 + 8 * INDIM;

    float v[8] = { p0[0], p0[1], p1[0], p1[1], p0[8], p0[9], p1[8], p1[9] };
    float h[8], l[8];
    #pragma unroll
    for (int i = 0; i < 8; i++) split2(v[i], h[i], l[i]);

    g_xhf[gid] = make_uint4(pbf2(h[0], h[1]), pbf2(h[2], h[3]),
                            pbf2(h[4], h[5]), pbf2(h[6], h[7]));
    g_xlf[gid] = make_uint4(pbf2(l[0], l[1]), pbf2(l[2], l[3]),
                            pbf2(l[4], l[5]), pbf2(l[6], l[7]));
}

// ---------------------------------------------------------------------------
// k0w: pack W1 into n8k16 B-fragment layout (col-major), hi/lo
// ---------------------------------------------------------------------------
__global__ __launch_bounds__(256) void k0_pack_w(const float* __restrict__ W1) {
    int gid = blockIdx.x * 256 + threadIdx.x;
    if (gid >= NGRP * KS49 * NT * 32) return;
    int lane = gid & 31;
    int t    = (gid >> 5) % NT;
    int ks   = ((gid >> 5) / NT) % KS49;
    int grp  = (gid >> 5) / (NT * KS49);

    int col = t * 8 + (lane >> 2);
    int net = grp * GNETS + col / ND;
    int c   = col % ND;
    int k0  = ks * 16 + (lane & 3) * 2;

    const float* wp = W1 + ((size_t)net * INDIM + k0) * ND + c;
    float v[4] = { wp[0], wp[ND], wp[8 * ND], wp[9 * ND] };
    float h[4], l[4];
    #pragma unroll
    for (int i = 0; i < 4; i++) split2(v[i], h[i], l[i]);

    g_wbhf[gid] = make_uint2(pbf2(h[0], h[1]), pbf2(h[2], h[3]));
    g_wblf[gid] = make_uint2(pbf2(l[0], l[1]), pbf2(l[2], l[3]));
}

// ---------------------------------------------------------------------------
// k0r: route -> fp16, reordered [o][n][kg][d][8k] (per-thread-contiguous)
// ---------------------------------------------------------------------------
__global__ __launch_bounds__(256) void k0_pack_r(const float* __restrict__ route) {
    int gid = blockIdx.x * 256 + threadIdx.x;      // ((o*30+n)*2+kg)*20 + d
    if (gid >= NOUT * NN * 2 * ND) return;
    int d  = gid % ND;
    int kg = (gid / ND) & 1;
    int on = gid / (ND * 2);                       // o*30+n
    const float* src = route + ((size_t)on * ND + d) * DK + kg * 8;
    float4 a = *(const float4*)src;
    float4 b = *(const float4*)(src + 4);
    uint4 q;
    __half2* hh = (__half2*)&q;
    hh[0] = __floats2half2_rn(a.x, a.y);
    hh[1] = __floats2half2_rn(a.z, a.w);
    hh[2] = __floats2half2_rn(b.x, b.y);
    hh[3] = __floats2half2_rn(b.z, b.w);
    *(uint4*)(g_rh + (size_t)gid * 8) = q;
}

// ---------------------------------------------------------------------------
// k1: HMMA split-bf16 GEMM1; B-fragments staged via cp.async double buffer.
// grid = (64, 5), block = 256 (8 warps x m16). N = 120.
// ---------------------------------------------------------------------------
__global__ __launch_bounds__(256, 2) void k1_mma(
    const float* __restrict__ b1,
    const float* __restrict__ W2,
    const float* __restrict__ b2)
{
    extern __shared__ __align__(16) char smk1[];
    uint4* bstage = (uint4*)smk1;                        // [2][BSTG] 15360 B
    float* hs  = (float*)(smk1 + 2 * BSTG * 16);         // [128][HSTR]
    float* ws2 = hs + 128 * HSTR;
    float* b1s = ws2 + GNETS * 400;
    float* b2s = b1s + GNETS * ND;

    const int tid  = threadIdx.x;
    const int w    = tid >> 5;
    const int lane = tid & 31;
    const int grp  = blockIdx.y;
    const int row0 = blockIdx.x * 128;

    // stage epilogue weights
    for (int it = tid; it < GNETS * 400; it += 256)
        ws2[it] = W2[(size_t)(grp * GNETS) * 400 + it];
    if (tid < GNETS * ND) {
        b1s[tid] = b1[grp * GNETS * ND + tid];
        b2s[tid] = b2[grp * GNETS * ND + tid];
    }

    float acc[NT][4];
    #pragma unroll
    for (int t = 0; t < NT; t++)
        #pragma unroll
        for (int i = 0; i < 4; i++) acc[t][i] = 0.f;

    const int band = blockIdx.x * 8 + w;
    const uint4* pah = g_xhf + (size_t)band * KS49 * 32 + lane;
    const uint4* pal = g_xlf + (size_t)band * KS49 * 32 + lane;
    const uint4* gbh = (const uint4*)(g_wbhf + (size_t)grp * KS49 * NT * 32);  // 240/ks
    const uint4* gbl = (const uint4*)(g_wblf + (size_t)grp * KS49 * NT * 32);

    const uint32_t bst_u32 = (uint32_t)__cvta_generic_to_shared(bstage);

    // issue one B stage (ks) into buffer buf via cp.async
    #define ISSUE_STAGE(ks, buf)                                                    \
        do {                                                                        \
            _Pragma("unroll")                                                       \
            for (int t_ = 0; t_ < 2; t_++) {                                        \
                int idx_ = tid + t_ * 256;                                          \
                if (idx_ < BSTG) {                                                  \
                    const uint4* src_ = (idx_ < 240)                                \
                        ? (gbh + (size_t)(ks) * 240 + idx_)                         \
                        : (gbl + (size_t)(ks) * 240 + (idx_ - 240));                \
                    uint32_t dst_ = bst_u32 + ((buf) * BSTG + idx_) * 16;           \
                    asm volatile("cp.async.cg.shared.global [%0], [%1], 16;"        \
                                 :: "r"(dst_), "l"(src_));                          \
                }                                                                   \
            }                                                                       \
            asm volatile("cp.async.commit_group;" ::: "memory");                    \
        } while (0)

    ISSUE_STAGE(0, 0);

    uint4 ah = pah[0];
    uint4 al = pal[0];
    for (int ks = 0; ks < KS49; ks++) {
        asm volatile("cp.async.wait_group 0;" ::: "memory");
        __syncthreads();
        if (ks + 1 < KS49) ISSUE_STAGE(ks + 1, (ks + 1) & 1);

        uint4 ah_n, al_n;
        if (ks + 1 < KS49) {                 // prefetch next A fragment
            ah_n = pah[(ks + 1) * 32];
            al_n = pal[(ks + 1) * 32];
        }

        const uint2* bb = (const uint2*)(bstage + (size_t)(ks & 1) * BSTG);
        #pragma unroll
        for (int t = 0; t < NT; t++) {
            uint2 vh = bb[t * 32 + lane];          // hi frags: uint2 idx 0..479
            uint2 vl = bb[BSTG + t * 32 + lane];   // lo frags follow (240 uint4)
            MMA_BF16(acc[t], ah, vh);
            MMA_BF16(acc[t], al, vh);
            MMA_BF16(acc[t], ah, vl);
        }
        ah = ah_n; al = al_n;
    }

    // accumulators -> smem
    {
        const int rlo = w * 16 + (lane >> 2);
        const int cb  = (lane & 3) * 2;
        #pragma unroll
        for (int t = 0; t < NT; t++) {
            int col = t * 8 + cb;
            hs[rlo * HSTR + col]           = acc[t][0];
            hs[rlo * HSTR + col + 1]       = acc[t][1];
            hs[(rlo + 8) * HSTR + col]     = acc[t][2];
            hs[(rlo + 8) * HSTR + col + 1] = acc[t][3];
        }
    }
    __syncthreads();

    // epilogue: bias+relu, GEMM2+relu, squash -> g_u (exact fp32)
    for (int task = tid; task < 128 * GNETS; task += 256) {
        const int row = task / GNETS;
        const int g   = task % GNETS;
        const int net = grp * GNETS + g;
        float h[ND];
        #pragma unroll
        for (int c = 0; c < ND; c++) {
            float v = hs[row * HSTR + g * ND + c] + b1s[g * ND + c];
            h[c] = v > 0.f ? v : 0.f;
        }
        float h2[ND];
        float sq = 0.f;
        #pragma unroll
        for (int e = 0; e < ND; e++) {
            float s = b2s[g * ND + e];
            #pragma unroll
            for (int d = 0; d < ND; d++) s += h[d] * ws2[g * 400 + d * ND + e];
            s = s > 0.f ? s : 0.f;
            h2[e] = s;
            sq += s * s;
        }
        float scale = (sq / (1.f + sq)) / sqrtf(sq);
        float* up = g_u + (size_t)(row0 + row) * (NN * ND) + net * ND;
        #pragma unroll
        for (int e4 = 0; e4 < 5; e4++)
            *(float4*)(up + e4 * 4) = make_float4(scale * h2[e4*4],   scale * h2[e4*4+1],
                                                  scale * h2[e4*4+2], scale * h2[e4*4+3]);
    }
}

// ---------------------------------------------------------------------------
// k2: fused priors + routing (fp16 route stream + fp16 priors in smem)
// grid = B/8, block 640, 105.6KB smem. (frozen from round 13)
// ---------------------------------------------------------------------------
__global__ __launch_bounds__(T2, 1) void k2_route(float* __restrict__ out) {
    extern __shared__ __align__(16) char smraw[];
    float*  u_s = (float*)smraw;
    float*  l_s  = (float*)smraw;
    float*  pr_s = l_s + RB * NOUT * NN;
    float*  v_s  = pr_s + RB * NOUT * NN;
    __half* p_h  = (__half*)(smraw + 600 * UPAD * 4);

    const int tid = threadIdx.x;
    const int r0  = blockIdx.x * RB;

    for (int it = tid; it < RB * NN * ND; it += T2) {
        int r = it / (NN * ND);
        int c = it % (NN * ND);
        u_s[c * UPAD + r] = g_u[(size_t)(r0 + r) * (NN * ND) + c];
    }
    __syncthreads();

    if (tid < 600) {
        const int n  = tid / 20;
        const int oo = tid % 20;
        const int o  = oo >> 1;
        const int kg = oo & 1;

        u64 acc[4][8];
        #pragma unroll
        for (int i = 0; i < 4; i++)
            #pragma unroll
            for (int j = 0; j < 8; j++) acc[i][j] = 0ull;

        const __half* rp = g_rh + ((size_t)(o * NN + n) * 2 + kg) * 160;
        const float*  up = u_s + (n * ND) * UPAD;

        #pragma unroll 4
        for (int d = 0; d < ND; d++) {
            ulonglong2 ua = *(const ulonglong2*)(up + d * UPAD);
            ulonglong2 ub = *(const ulonglong2*)(up + d * UPAD + 4);
            u64 uv[4] = {ua.x, ua.y, ub.x, ub.y};
            uint4 q = *(const uint4*)(rp + d * 8);
            __half2* hh = (__half2*)&q;
            float2 f0 = __half22float2(hh[0]);
            float2 f1 = __half22float2(hh[1]);
            float2 f2 = __half22float2(hh[2]);
            float2 f3 = __half22float2(hh[3]);
            u64 wv[8] = {pack2(f0.x, f0.x), pack2(f0.y, f0.y),
                         pack2(f1.x, f1.x), pack2(f1.y, f1.y),
                         pack2(f2.x, f2.x), pack2(f2.y, f2.y),
                         pack2(f3.x, f3.x), pack2(f3.y, f3.y)};
            #pragma unroll
            for (int i = 0; i < 4; i++)
                #pragma unroll
                for (int j = 0; j < 8; j++)
                    fma2(acc[i][j], uv[i], wv[j]);
        }

        #pragma unroll
        for (int i = 0; i < 4; i++) {
            float lo[8], hi[8];
            #pragma unroll
            for (int j = 0; j < 8; j++) unpack2(acc[i][j], lo[j], hi[j]);
            uint4 qlo, qhi;
            __half2* a = (__half2*)&qlo;
            __half2* b = (__half2*)&qhi;
            #pragma unroll
            for (int p = 0; p < 4; p++) {
                a[p] = __floats2half2_rn(lo[2*p], lo[2*p + 1]);
                b[p] = __floats2half2_rn(hi[2*p], hi[2*p + 1]);
            }
            *(uint4*)&p_h[((((2*i    ) * NOUT + o) * NN + n) * DK) + kg * 8] = qlo;
            *(uint4*)&p_h[((((2*i + 1) * NOUT + o) * NN + n) * DK) + kg * 8] = qhi;
        }
    }
    __syncthreads();

    for (int iter = 0; iter < 3; iter++) {
        if (iter > 0) {
            if (tid < RB * NN) {
                int r = tid / NN, n = tid % NN;
                float l[NOUT];
                float mx = -1e30f;
                #pragma unroll
                for (int o = 0; o < NOUT; o++) {
                    l[o] = l_s[(r * NOUT + o) * NN + n];
                    mx = fmaxf(mx, l[o]);
                }
                float ssum = 0.f;
                #pragma unroll
                for (int o = 0; o < NOUT; o++) { l[o] = expf(l[o] - mx); ssum += l[o]; }
                float inv = 1.f / ssum;
                #pragma unroll
                for (int o = 0; o < NOUT; o++)
                    pr_s[(r * NOUT + o) * NN + n] = l[o] * inv;
            }
            __syncthreads();
        }

        if (tid < RB * NOUT * 2) {
            int kh = tid & 1;
            int ro = tid >> 1;
            const __half* pp = p_h + ro * (NN * DK) + kh * 8;
            float s8[8] = {0,0,0,0,0,0,0,0};
            #pragma unroll 5
            for (int n = 0; n < NN; n++) {
                uint4 q = *(const uint4*)(pp + n * DK);
                __half2* hx = (__half2*)&q;
                float w = (iter == 0) ? 1.f : pr_s[ro * NN + n];
                #pragma unroll
                for (int p = 0; p < 4; p++) {
                    float2 f = __half22float2(hx[p]);
                    s8[2*p]   += w * f.x;
                    s8[2*p+1] += w * f.y;
                }
            }
            float mul = (iter == 0) ? 0.1f : 1.f;
            #pragma unroll
            for (int j = 0; j < 8; j++) v_s[ro * DK + kh * 8 + j] = s8[j] * mul;
        }
        __syncthreads();

        if (tid < RB * NOUT) {
            float* vp = v_s + tid * DK;
            float sq = 0.f;
            #pragma unroll
            for (int k = 0; k < DK; k++) sq += vp[k] * vp[k];
            float scale = (sq / (1.f + sq)) / sqrtf(sq);
            #pragma unroll
            for (int k = 0; k < DK; k++) vp[k] *= scale;
        }
        __syncthreads();

        if (iter < 2) {
            for (int it = tid; it < RB * NOUT * NN; it += T2) {
                int n  = it % NN;
                int ro = it / NN;
                const __half* pp = p_h + ro * (NN * DK) + n * DK;
                const float* vp = v_s + ro * DK;
                uint4 q0 = *(const uint4*)pp;
                uint4 q1 = *(const uint4*)(pp + 8);
                __half2* h0 = (__half2*)&q0;
                __half2* h1 = (__half2*)&q1;
                float s = 0.f;
                #pragma unroll
                for (int p = 0; p < 4; p++) {
                    float2 f0 = __half22float2(h0[p]);
                    float2 f1 = __half22float2(h1[p]);
                    s += f0.x * vp[2*p]     + f0.y * vp[2*p + 1];
                    s += f1.x * vp[8 + 2*p] + f1.y * vp[8 + 2*p + 1];
                }
                l_s[ro * NN + n] = (iter == 0) ? s : (l_s[ro * NN + n] + s);
            }
            __syncthreads();
        }
    }

    for (int it = tid; it < RB * NOUT * DK; it += T2) {
        int r = it / (NOUT * DK);
        out[(size_t)(r0 + r) * (NOUT * DK) + (it % (NOUT * DK))] = v_s[it];
    }
}

// ---------------------------------------------------------------------------
extern "C" void kernel_launch(void* const* d_in, const int* in_sizes, int n_in,
                              void* d_out, int out_size)
{
    const float* x     = (const float*)d_in[0];
    const float* W1    = (const float*)d_in[1];
    const float* b1    = (const float*)d_in[2];
    const float* W2    = (const float*)d_in[3];
    const float* b2    = (const float*)d_in[4];
    const float* route = (const float*)d_in[5];
    float* out = (float*)d_out;

    // pack inputs (HMMA frags bf16 hi/lo; route fp16 reordered)
    k0_pack_x<<<(NBAND * KS49 * 32 + 255) / 256, 256>>>(x);
    k0_pack_w<<<(NGRP * KS49 * NT * 32 + 255) / 256, 256>>>(W1);
    k0_pack_r<<<(NOUT * NN * 2 * ND + 255) / 256, 256>>>(route);

    // tensor-core GEMM1 + fused epilogue (B staged via cp.async)
    const int smem1 = 2 * BSTG * 16
                    + (128 * HSTR + GNETS * 400 + 2 * GNETS * ND) * (int)sizeof(float);
    cudaFuncSetAttribute(k1_mma, cudaFuncAttributeMaxDynamicSharedMemorySize, smem1);
    dim3 g1(B_TOTAL / 128, NGRP);
    k1_mma<<<g1, 256, smem1>>>(b1, W2, b2);

    // fused priors + routing (fp16 route stream + fp16 priors in smem)
    const int smem2 = 600 * UPAD * (int)sizeof(float)
                    + RB * NOUT * NN * DK * (int)sizeof(__half);   // 105,600 B
    cudaFuncSetAttribute(k2_route, cudaFuncAttributeMaxDynamicSharedMemorySize, smem2);
    k2_route<<<B_TOTAL / RB, T2, smem2>>>(out);
}